// round 8
// baseline (speedup 1.0000x reference)
#include <cuda_runtime.h>

// out[b, h, w] = 0.5f * (x[b,0,h,w] + x[b,1,h,w] + x[b,2,h,w])
// x: (16, 3, 1024, 1024) f32, out: (16, 1, 1024, 1024) f32.
// HBM-bound streaming reduction. R7: 4 float4 outputs per thread
// (12 independent LDG.128 front-batched) + .cs streaming hints.

static constexpr int B = 16;
static constexpr int C = 3;
static constexpr int HW = 1024 * 1024;
static constexpr int HW4 = HW / 4;          // float4 per plane = 2^18
static constexpr int NOUT4 = B * HW4;       // 4M float4 outputs
static constexpr int TPB = 256;
static constexpr int VPT = 4;               // float4 outputs per thread
static constexpr int PER_BLOCK = TPB * VPT; // 1024 float4 per block

__global__ __launch_bounds__(TPB) void haar_sum_kernel(
    const float4* __restrict__ in, float4* __restrict__ out)
{
    int j0 = blockIdx.x * PER_BLOCK + threadIdx.x;

    int b = j0 >> 18;                         // PER_BLOCK=1024 divides 2^18: one batch per block
    const float4* base = in + (size_t)b * (C * HW4);

    int p[VPT];
    #pragma unroll
    for (int v = 0; v < VPT; v++)
        p[v] = (j0 + v * TPB) & (HW4 - 1);

    // 12 independent streaming loads front-batched
    float4 a[VPT], bb[VPT], cc[VPT];
    #pragma unroll
    for (int v = 0; v < VPT; v++) a[v]  = __ldcs(base + p[v]);
    #pragma unroll
    for (int v = 0; v < VPT; v++) bb[v] = __ldcs(base + HW4 + p[v]);
    #pragma unroll
    for (int v = 0; v < VPT; v++) cc[v] = __ldcs(base + 2 * HW4 + p[v]);

    #pragma unroll
    for (int v = 0; v < VPT; v++) {
        float4 r;
        r.x = 0.5f * (a[v].x + bb[v].x + cc[v].x);
        r.y = 0.5f * (a[v].y + bb[v].y + cc[v].y);
        r.z = 0.5f * (a[v].z + bb[v].z + cc[v].z);
        r.w = 0.5f * (a[v].w + bb[v].w + cc[v].w);
        __stcs(out + j0 + v * TPB, r);
    }
}

extern "C" void kernel_launch(void* const* d_in, const int* in_sizes, int n_in,
                              void* d_out, int out_size)
{
    const float4* in = (const float4*)d_in[0];
    float4* out = (float4*)d_out;

    int blocks = NOUT4 / PER_BLOCK;   // 4096, exact
    haar_sum_kernel<<<blocks, TPB>>>(in, out);
}